// round 9
// baseline (speedup 1.0000x reference)
#include <cuda_runtime.h>
#include <math.h>

// Shapes
//   amplitudes, frequencies : [8, 250, 100] f32
//   out = concat( amp_env [8, 64000, 100], freq_env [8, 250, 100] )  f32
#define B            8
#define FRAMES       250
#define CH           100
#define CTRL_ELEMS   (B * FRAMES * CH)        // 200000
#define T_OUT        64000
#define HOP          256                      // 64000 / 250
#define ENV_ELEMS    (B * T_OUT * CH)         // 51200000
#define SEGS         (B * FRAMES)             // 2000 segments
#define SEG_VEC4     (HOP * (CH / 4))         // 6400 float4 per segment
#define BLK_PER_SEG  25                       // 6400 / 256
#define UP_GRID      (SEGS * BLK_PER_SEG)     // 50000 blocks

// Scratch (no cudaMalloc allowed): masked amps as float4 rows + window table.
__device__ __align__(16) float4 g_amps4[SEGS * (CH / 4)];
__device__ float g_win[HOP];

// ---------------------------------------------------------------------------
// Kernel 1: get_controls — amp scaling, freq sigmoid mapping, nyquist mask.
// Also builds the 256-entry hann half-window table (block 0).
// ---------------------------------------------------------------------------
__global__ void controls_kernel(const float* __restrict__ amp_in,
                                const float* __restrict__ freq_in,
                                float* __restrict__ freq_out) {
    const int idx = blockIdx.x * blockDim.x + threadIdx.x;

    if (blockIdx.x == 0 && threadIdx.x < HOP) {
        g_win[threadIdx.x] =
            0.5f - 0.5f * cospif((float)threadIdx.x * (1.0f / 256.0f));
    }
    if (idx >= CTRL_ELEMS) return;

    const float LOG10_F  = 2.302585092994046f;   // ln(10)
    const float MIDI_MAX = 119.21309485364912f;  // 12*(log2 8000-log2 440)+69
    const float NYQ      = 22050.0f;             // SR / 2

    // frequencies_sigmoid
    float f  = freq_in[idx];
    float uf = 1.0f / (1.0f + expf(-f));
    float freq = 440.0f * exp2f((uf * MIDI_MAX - 69.0f) * (1.0f / 12.0f));

    // scale_function: 2 * sigmoid(a)^ln(10) + 1e-7
    float a  = amp_in[idx];
    float sa = 1.0f / (1.0f + expf(-a));
    float amp = 2.0f * powf(sa, LOG10_F) + 1e-7f;

    // remove_above_nyquist: harmonic = (idx % 100) + 1
    int c = idx - (idx / CH) * CH;
    float aa = ((freq * (float)(c + 1) < NYQ) ? 1.0f : 0.0f) + 1e-4f;

    reinterpret_cast<float*>(g_amps4)[idx] = amp * aa;
    freq_out[idx] = freq;
}

// ---------------------------------------------------------------------------
// Kernel 2: flat-grid 2-tap hann crossfade (R2 structure, leaner issue).
// Grid = 2000 segments x 25 blocks of 256 threads; each thread stores ONE
// float4. No barriers, no divisions by 100, window from a precomputed table:
//   out[seg*6400 + v] = x0 + (x1 - x0) * g_win[v/25]
// where c4 = v % 25 selects the channel float4-group, x0/x1 are the segment
// endpoint rows (L1-hot: 25 distinct float4 per block, reused 256x).
// ---------------------------------------------------------------------------
__global__ __launch_bounds__(256) void upsample_kernel(float4* __restrict__ out) {
    const int bid = blockIdx.x;
    const int seg  = bid / BLK_PER_SEG;              // const-div -> mul/shift
    const int vblk = bid - seg * BLK_PER_SEG;        // 0..24
    const int v    = vblk * 256 + threadIdx.x;       // 0..6399 within segment

    const int row = v / 25;                          // 0..255 (const-div)
    const int c4  = v - row * 25;                    // channel float4-group

    int segn = seg + 1;
    if (seg - (seg / FRAMES) * FRAMES == FRAMES - 1) // batch-edge clamp
        segn = seg;

    const float w = g_win[row];

    const float4 x0 = g_amps4[seg  * 25 + c4];
    const float4 x1 = g_amps4[segn * 25 + c4];

    float4 o;
    o.x = fmaf(x1.x - x0.x, w, x0.x);
    o.y = fmaf(x1.y - x0.y, w, x0.y);
    o.z = fmaf(x1.z - x0.z, w, x0.z);
    o.w = fmaf(x1.w - x0.w, w, x0.w);

    out[(size_t)seg * SEG_VEC4 + v] = o;
}

// ---------------------------------------------------------------------------
extern "C" void kernel_launch(void* const* d_in, const int* in_sizes, int n_in,
                              void* d_out, int out_size) {
    const float* amps  = (const float*)d_in[0];
    const float* freqs = (const float*)d_in[1];
    float* out = (float*)d_out;

    controls_kernel<<<(CTRL_ELEMS + 255) / 256, 256>>>(amps, freqs,
                                                       out + ENV_ELEMS);
    upsample_kernel<<<UP_GRID, 256>>>((float4*)out);
}

// round 10
// speedup vs baseline: 1.2848x; 1.2848x over previous
#include <cuda_runtime.h>
#include <math.h>

// Shapes
//   amplitudes, frequencies : [8, 250, 100] f32
//   out = concat( amp_env [8, 64000, 100], freq_env [8, 250, 100] )  f32
#define B            8
#define FRAMES       250
#define CH           100
#define CTRL_ELEMS   (B * FRAMES * CH)        // 200000
#define T_OUT        64000
#define HOP          256                      // 64000 / 250
#define ENV_ELEMS    (B * T_OUT * CH)         // 51200000
#define SEGS         (B * FRAMES)             // 2000 segments
#define SEG_VEC4     (HOP * (CH / 4))         // 6400 float4 per segment
#define UP_THREADS   400                      // 16 rows x 25 float4-groups
#define STORES       16                       // float4 stores per thread

// Scratch for scaled+nyquist-masked amplitudes (no cudaMalloc allowed).
__device__ __align__(16) float g_amps[CTRL_ELEMS];

// ---------------------------------------------------------------------------
// Kernel 1: get_controls — amp scaling, freq sigmoid mapping, nyquist mask.
// Writes freqs directly into the tail of d_out, masked amps into g_amps.
// ---------------------------------------------------------------------------
__global__ void controls_kernel(const float* __restrict__ amp_in,
                                const float* __restrict__ freq_in,
                                float* __restrict__ freq_out) {
    int idx = blockIdx.x * blockDim.x + threadIdx.x;
    if (idx >= CTRL_ELEMS) return;

    const float LOG10_F   = 2.302585092994046f;   // ln(10)
    const float MIDI_MAX  = 119.21309485364912f;  // 12*(log2 8000-log2 440)+69
    const float NYQ       = 22050.0f;             // SR / 2

    // frequencies_sigmoid
    float f  = freq_in[idx];
    float uf = 1.0f / (1.0f + expf(-f));
    float freq = 440.0f * exp2f((uf * MIDI_MAX - 69.0f) * (1.0f / 12.0f));

    // scale_function: 2 * sigmoid(a)^ln(10) + 1e-7
    float a  = amp_in[idx];
    float sa = 1.0f / (1.0f + expf(-a));
    float amp = 2.0f * powf(sa, LOG10_F) + 1e-7f;

    // remove_above_nyquist: harmonic index = (idx % 100) + 1
    int k = idx - (idx / CH) * CH;            // channel index 0..99
    float h = (float)(k + 1);
    float aa = ((freq * h < NYQ) ? 1.0f : 0.0f) + 1e-4f;

    g_amps[idx]  = amp * aa;
    freq_out[idx] = freq;
}

// ---------------------------------------------------------------------------
// Kernel 2: register-resident 2-tap hann crossfade, 16 stores per thread.
//
// One block per segment (b, j). Thread tid owns fixed channel float4-group
// c4 = tid % 25 and base row r0 = tid / 25 (0..15); endpoints x0/x1 loaded
// ONCE from g_amps, d = x1 - x0, then 16 fully coalesced float4 stores:
//   iteration k writes float4 index seg*6400 + 400k + tid, whose row is
//   16k + r0 and channel group c4, with weight w = sw[r0 + 16k],
//   out = x0 + d * w,  w[r] = 0.5 - 0.5*cospi(r/256).
// 2 LDG.128 per 256 B stored (half of the 800-thread variant) and 16
// independent STG.128 in flight per thread.
// ---------------------------------------------------------------------------
__global__ __launch_bounds__(UP_THREADS) void upsample_kernel(
        float4* __restrict__ out) {
    __shared__ float sw[HOP];

    const int tid = threadIdx.x;
    const int seg = blockIdx.x;

    if (tid < HOP) {
        sw[tid] = 0.5f - 0.5f * cospif((float)tid * (1.0f / 256.0f));
    }

    int segn = seg + 1;
    if (segn % FRAMES == 0) segn = seg;       // clamp: frame 250 == frame 249

    const int c4 = tid % 25;                  // channel float4-group (fixed)
    const int r0 = tid / 25;                  // base row (0..15)

    __syncthreads();

    const float4 x0 = *reinterpret_cast<const float4*>(&g_amps[seg  * CH + c4 * 4]);
    const float4 x1 = *reinterpret_cast<const float4*>(&g_amps[segn * CH + c4 * 4]);
    float4 d;
    d.x = x1.x - x0.x;
    d.y = x1.y - x0.y;
    d.z = x1.z - x0.z;
    d.w = x1.w - x0.w;

    float4* o = out + (size_t)seg * SEG_VEC4 + tid;

#pragma unroll
    for (int k = 0; k < STORES; k++) {
        const float w = sw[r0 + 16 * k];
        float4 v;
        v.x = fmaf(d.x, w, x0.x);
        v.y = fmaf(d.y, w, x0.y);
        v.z = fmaf(d.z, w, x0.z);
        v.w = fmaf(d.w, w, x0.w);
        o[UP_THREADS * k] = v;
    }
}

// ---------------------------------------------------------------------------
extern "C" void kernel_launch(void* const* d_in, const int* in_sizes, int n_in,
                              void* d_out, int out_size) {
    const float* amps  = (const float*)d_in[0];
    const float* freqs = (const float*)d_in[1];
    float* out = (float*)d_out;

    controls_kernel<<<(CTRL_ELEMS + 255) / 256, 256>>>(amps, freqs,
                                                       out + ENV_ELEMS);
    upsample_kernel<<<SEGS, UP_THREADS>>>((float4*)out);
}